// round 1
// baseline (speedup 1.0000x reference)
#include <cuda_runtime.h>
#include <math.h>

#define BATCH 4
#define CH    512
#define LEN   2048

// Scratch (no allocations allowed): conv outputs + attention output, [B,C,L] fp32 each.
__device__ float g_yq[BATCH*CH*LEN];
__device__ float g_yk[BATCH*CH*LEN];
__device__ float g_yv[BATCH*CH*LEN];
__device__ float g_z [BATCH*CH*LEN];

// ---------------------------------------------------------------------------
// Conv1d (kernel=3, 'same' zero padding) as a tiled GEMM.
// Block: 64 out-channels x 64 positions for one batch. 256 threads, 4x4 micro.
// ---------------------------------------------------------------------------
__global__ __launch_bounds__(256)
void conv1d_k(const float* __restrict__ x, const float* __restrict__ w,
              const float* __restrict__ bias, float* __restrict__ y)
{
    __shared__ float Ws[48][65];   // [ci*3+t][co], pitch 65 => conflict-free stores
    __shared__ float Xs[16][66];   // [ci][l0-1 .. l0+64]

    const int tid = threadIdx.x;
    const int tx = tid & 15, ty = tid >> 4;
    const int b   = blockIdx.z;
    const int co0 = blockIdx.y << 6;
    const int l0  = blockIdx.x << 6;
    const float* xb = x + (size_t)b * (CH * LEN);

    float acc[4][4] = {};

    for (int ci0 = 0; ci0 < CH; ci0 += 16) {
        __syncthreads();
        // Load X tile: 16 channels x 66 positions (with halo, zero-padded)
        for (int idx = tid; idx < 16 * 66; idx += 256) {
            int r = idx / 66, c = idx - r * 66;
            int gl = l0 - 1 + c;
            Xs[r][c] = (gl >= 0 && gl < LEN) ? xb[(ci0 + r) * LEN + gl] : 0.f;
        }
        // Load W tile: 64 co x (16 ci x 3 taps). Global layout [co][ci][t].
        for (int idx = tid; idx < 64 * 48; idx += 256) {
            int co = idx / 48, r = idx - co * 48;     // r = ci_local*3 + t
            Ws[r][co] = w[(size_t)(co0 + co) * (CH * 3) + ci0 * 3 + r];
        }
        __syncthreads();

        #pragma unroll
        for (int ci = 0; ci < 16; ci++) {
            #pragma unroll
            for (int t = 0; t < 3; t++) {
                float wv[4], xv[4];
                #pragma unroll
                for (int a = 0; a < 4; a++) wv[a] = Ws[ci * 3 + t][(ty << 2) + a];
                #pragma unroll
                for (int c = 0; c < 4; c++) xv[c] = Xs[ci][(tx << 2) + c + t];
                #pragma unroll
                for (int a = 0; a < 4; a++)
                    #pragma unroll
                    for (int c = 0; c < 4; c++)
                        acc[a][c] = fmaf(wv[a], xv[c], acc[a][c]);
            }
        }
    }

    #pragma unroll
    for (int a = 0; a < 4; a++) {
        float bv = bias[co0 + (ty << 2) + a];
        float4 r4 = make_float4(acc[a][0] + bv, acc[a][1] + bv,
                                acc[a][2] + bv, acc[a][3] + bv);
        *(float4*)(y + ((size_t)b * CH + co0 + (ty << 2) + a) * LEN
                     + l0 + (tx << 2)) = r4;
    }
}

// ---------------------------------------------------------------------------
// Flash-style attention over the torch-faithful reshape:
//   A[b,h,n,d] = convout[b, n>>2, (n&3)*512 + h*64 + d]   (64 contiguous floats)
// Block: one (b, h, 64-query tile). 256 threads, 4x4 micro-tiles.
// Smem = exactly 48KB: Qs + (K^T xor-swizzled, reused as P) + Vs.
// ---------------------------------------------------------------------------
__global__ __launch_bounds__(256)
void attn_k(const float* __restrict__ yq, const float* __restrict__ yk,
            const float* __restrict__ yv, float* __restrict__ z)
{
    __shared__ float Qs[64][64];
    __shared__ float KP[64][64];   // K^T (xor swizzle), then P
    __shared__ float Vs[64][64];

    const int tid = threadIdx.x;
    const int tx = tid & 15, ty = tid >> 4;
    const int b = blockIdx.z, h = blockIdx.y;
    const int t0 = blockIdx.x << 6;
    const size_t bbase = (size_t)b * (CH * LEN);
    const int hoff = h << 6;

    // Load Q tile (rows = queries, cols = d; contiguous float4 in global)
    for (int idx = tid; idx < 1024; idx += 256) {
        int r = idx >> 4, ch = idx & 15;
        int n = t0 + r;
        size_t off = bbase + (size_t)(n >> 2) * LEN + (n & 3) * 512 + hoff + (ch << 2);
        *(float4*)&Qs[r][ch << 2] = *(const float4*)(yq + off);
    }

    float m[4], lsum[4], o[4][4];
    #pragma unroll
    for (int a = 0; a < 4; a++) {
        m[a] = -INFINITY; lsum[a] = 0.f;
        #pragma unroll
        for (int c = 0; c < 4; c++) o[a][c] = 0.f;
    }

    for (int j0 = 0; j0 < LEN; j0 += 64) {
        __syncthreads();  // prev-iter readers of KP/Vs done; also fences Q load
        // Load K (transposed + swizzled) and V tiles
        for (int idx = tid; idx < 1024; idx += 256) {
            int r = idx >> 4, ch = idx & 15;
            int n = j0 + r;
            size_t off = bbase + (size_t)(n >> 2) * LEN + (n & 3) * 512 + hoff + (ch << 2);
            float4 kv4 = *(const float4*)(yk + off);
            int sw = r ^ (ch << 2);       // col swizzle: r ^ (row & 60)
            KP[(ch << 2) + 0][sw] = kv4.x;
            KP[(ch << 2) + 1][sw] = kv4.y;
            KP[(ch << 2) + 2][sw] = kv4.z;
            KP[(ch << 2) + 3][sw] = kv4.w;
            float4 vv4 = *(const float4*)(yv + off);
            *(float4*)&Vs[r][ch << 2] = vv4;
        }
        __syncthreads();

        // S = Q @ K^T  (scaled by 1/64 afterwards)
        float s[4][4] = {};
        #pragma unroll 8
        for (int d = 0; d < 64; d++) {
            float qv[4], kv[4];
            #pragma unroll
            for (int a = 0; a < 4; a++) qv[a] = Qs[(ty << 2) + a][d];
            const int dm = d & 60;
            #pragma unroll
            for (int c = 0; c < 4; c++) kv[c] = KP[d][((tx << 2) + c) ^ dm];
            #pragma unroll
            for (int a = 0; a < 4; a++)
                #pragma unroll
                for (int c = 0; c < 4; c++)
                    s[a][c] = fmaf(qv[a], kv[c], s[a][c]);
        }
        __syncthreads();  // everyone done reading KP before it becomes P

        // Online softmax update; write P into KP (plain [i][j] layout)
        #pragma unroll
        for (int a = 0; a < 4; a++) {
            const float scale = 1.f / 64.f;
            float s0 = s[a][0] * scale, s1 = s[a][1] * scale;
            float s2 = s[a][2] * scale, s3 = s[a][3] * scale;
            float mx = fmaxf(fmaxf(s0, s1), fmaxf(s2, s3));
            mx = fmaxf(mx, __shfl_xor_sync(0xffffffffu, mx, 8));
            mx = fmaxf(mx, __shfl_xor_sync(0xffffffffu, mx, 4));
            mx = fmaxf(mx, __shfl_xor_sync(0xffffffffu, mx, 2));
            mx = fmaxf(mx, __shfl_xor_sync(0xffffffffu, mx, 1));
            float newm = fmaxf(m[a], mx);
            float corr = __expf(m[a] - newm);
            float p0 = __expf(s0 - newm);
            float p1 = __expf(s1 - newm);
            float p2 = __expf(s2 - newm);
            float p3 = __expf(s3 - newm);
            float rs = (p0 + p1) + (p2 + p3);
            rs += __shfl_xor_sync(0xffffffffu, rs, 8);
            rs += __shfl_xor_sync(0xffffffffu, rs, 4);
            rs += __shfl_xor_sync(0xffffffffu, rs, 2);
            rs += __shfl_xor_sync(0xffffffffu, rs, 1);
            lsum[a] = lsum[a] * corr + rs;
            m[a] = newm;
            o[a][0] *= corr; o[a][1] *= corr; o[a][2] *= corr; o[a][3] *= corr;
            KP[(ty << 2) + a][(tx << 2) + 0] = p0;
            KP[(ty << 2) + a][(tx << 2) + 1] = p1;
            KP[(ty << 2) + a][(tx << 2) + 2] = p2;
            KP[(ty << 2) + a][(tx << 2) + 3] = p3;
        }
        __syncthreads();

        // O += P @ V
        #pragma unroll 8
        for (int j = 0; j < 64; j++) {
            float pv[4], vv[4];
            #pragma unroll
            for (int a = 0; a < 4; a++) pv[a] = KP[(ty << 2) + a][j];
            #pragma unroll
            for (int c = 0; c < 4; c++) vv[c] = Vs[j][(tx << 2) + c];
            #pragma unroll
            for (int a = 0; a < 4; a++)
                #pragma unroll
                for (int c = 0; c < 4; c++)
                    o[a][c] = fmaf(pv[a], vv[c], o[a][c]);
        }
    }

    // Epilogue: normalize, write to final-conv input layout
    #pragma unroll
    for (int a = 0; a < 4; a++) {
        float inv = 1.f / lsum[a];
        int n = t0 + (ty << 2) + a;
        size_t off = bbase + (size_t)(n >> 2) * LEN + (n & 3) * 512 + hoff + (tx << 2);
        float4 r4 = make_float4(o[a][0] * inv, o[a][1] * inv,
                                o[a][2] * inv, o[a][3] * inv);
        *(float4*)(z + off) = r4;
    }
}

// ---------------------------------------------------------------------------
extern "C" void kernel_launch(void* const* d_in, const int* in_sizes, int n_in,
                              void* d_out, int out_size)
{
    const float* q    = (const float*)d_in[0];
    const float* k    = (const float*)d_in[1];
    const float* v    = (const float*)d_in[2];
    const float* wq_w = (const float*)d_in[3];
    const float* wq_b = (const float*)d_in[4];
    const float* wk_w = (const float*)d_in[5];
    const float* wk_b = (const float*)d_in[6];
    const float* wv_w = (const float*)d_in[7];
    const float* wv_b = (const float*)d_in[8];
    const float* fc_w = (const float*)d_in[9];
    const float* fc_b = (const float*)d_in[10];
    float* out = (float*)d_out;

    float *yq, *yk, *yv, *zb;
    cudaGetSymbolAddress((void**)&yq, g_yq);
    cudaGetSymbolAddress((void**)&yk, g_yk);
    cudaGetSymbolAddress((void**)&yv, g_yv);
    cudaGetSymbolAddress((void**)&zb, g_z);

    dim3 grid(LEN / 64, CH / 64, BATCH);   // (32, 8, 4)
    dim3 blk(256);
    conv1d_k<<<grid, blk>>>(q, wq_w, wq_b, yq);
    conv1d_k<<<grid, blk>>>(k, wk_w, wk_b, yk);
    conv1d_k<<<grid, blk>>>(v, wv_w, wv_b, yv);

    dim3 agrid(LEN / 64, 8, BATCH);        // (32 q-tiles, H, B)
    attn_k<<<agrid, blk>>>(yq, yk, yv, zb);

    conv1d_k<<<grid, blk>>>(zb, fc_w, fc_b, out);
}

// round 2
// speedup vs baseline: 1.1330x; 1.1330x over previous
#include <cuda_runtime.h>
#include <math.h>

#define BATCH 4
#define CH    512
#define LEN   2048

__device__ float g_yq[BATCH*CH*LEN];
__device__ float g_yk[BATCH*CH*LEN];
__device__ float g_yv[BATCH*CH*LEN];
__device__ float g_z [BATCH*CH*LEN];

// ---------------------------------------------------------------------------
// Conv1d (k=3, same) tiled GEMM body. 64co x 64pos tile, 256 threads, 4x4 micro.
// X window vectorized (LDS.128 + 2 scalars per ci, reused across taps).
// ---------------------------------------------------------------------------
__device__ __forceinline__
void conv_body(const float* __restrict__ x, const float* __restrict__ w,
               const float* __restrict__ bias, float* __restrict__ y,
               int b, int co0, int l0)
{
    __shared__ float Ws[48][65];   // [ci*3+t][co], pitch 65: conflict-free stores
    __shared__ float Xs[16][68];   // [ci][pos l0-1 .. l0+64], pitch 68: 16B-aligned rows

    const int tid = threadIdx.x;
    const int tx = tid & 15, ty = tid >> 4;
    const float* xb = x + (size_t)b * (CH * LEN);

    float acc[4][4] = {};

    for (int ci0 = 0; ci0 < CH; ci0 += 16) {
        __syncthreads();
        for (int idx = tid; idx < 16 * 66; idx += 256) {
            int r = idx / 66, c = idx - r * 66;
            int gl = l0 - 1 + c;
            Xs[r][c] = (gl >= 0 && gl < LEN) ? xb[(ci0 + r) * LEN + gl] : 0.f;
        }
        for (int idx = tid; idx < 64 * 48; idx += 256) {
            int co = idx / 48, r = idx - co * 48;     // r = ci_local*3 + t
            Ws[r][co] = w[(size_t)(co0 + co) * (CH * 3) + ci0 * 3 + r];
        }
        __syncthreads();

        #pragma unroll
        for (int ci = 0; ci < 16; ci++) {
            // 6-float X window covering taps 0..2 for 4 output positions
            float xw[6];
            float4 x4 = *(const float4*)&Xs[ci][tx << 2];
            xw[0] = x4.x; xw[1] = x4.y; xw[2] = x4.z; xw[3] = x4.w;
            xw[4] = Xs[ci][(tx << 2) + 4];
            xw[5] = Xs[ci][(tx << 2) + 5];
            #pragma unroll
            for (int t = 0; t < 3; t++) {
                float wv[4];
                #pragma unroll
                for (int a = 0; a < 4; a++) wv[a] = Ws[ci * 3 + t][(ty << 2) + a];
                #pragma unroll
                for (int a = 0; a < 4; a++)
                    #pragma unroll
                    for (int c = 0; c < 4; c++)
                        acc[a][c] = fmaf(wv[a], xw[c + t], acc[a][c]);
            }
        }
    }

    #pragma unroll
    for (int a = 0; a < 4; a++) {
        float bv = bias[co0 + (ty << 2) + a];
        float4 r4 = make_float4(acc[a][0] + bv, acc[a][1] + bv,
                                acc[a][2] + bv, acc[a][3] + bv);
        *(float4*)(y + ((size_t)b * CH + co0 + (ty << 2) + a) * LEN
                     + l0 + (tx << 2)) = r4;
    }
}

// Fused Q/K/V convs: blockIdx.z in [0,12): sel = z>>2, b = z&3.
__global__ __launch_bounds__(256)
void conv_qkv_k(const float* __restrict__ q, const float* __restrict__ k,
                const float* __restrict__ v,
                const float* __restrict__ wq, const float* __restrict__ wk,
                const float* __restrict__ wv,
                const float* __restrict__ bq, const float* __restrict__ bk,
                const float* __restrict__ bv,
                float* __restrict__ yq, float* __restrict__ yk,
                float* __restrict__ yv)
{
    int sel = blockIdx.z >> 2, b = blockIdx.z & 3;
    const float* x; const float* w; const float* bia; float* y;
    if (sel == 0)      { x = q; w = wq; bia = bq; y = yq; }
    else if (sel == 1) { x = k; w = wk; bia = bk; y = yk; }
    else               { x = v; w = wv; bia = bv; y = yv; }
    conv_body(x, w, bia, y, b, blockIdx.y << 6, blockIdx.x << 6);
}

__global__ __launch_bounds__(256)
void conv1d_k(const float* __restrict__ x, const float* __restrict__ w,
              const float* __restrict__ bias, float* __restrict__ y)
{
    conv_body(x, w, bias, y, blockIdx.z, blockIdx.y << 6, blockIdx.x << 6);
}

// ---------------------------------------------------------------------------
// Flash attention. Torch-faithful reshape:
//   A[b,h,n,d] = convout[b, n>>2, (n&3)*512 + h*64 + d]  (64 contiguous floats)
// Q stored transposed+swizzled; K^T swizzled; both operands read as LDS.128.
// ---------------------------------------------------------------------------
__global__ __launch_bounds__(256)
void attn_k(const float* __restrict__ yq, const float* __restrict__ yk,
            const float* __restrict__ yv, float* __restrict__ z)
{
    __shared__ float QsT[64][64];  // [d][n ^ (d&60)]
    __shared__ float KP [64][64];  // K^T [d][j ^ (d&60)], then P [i][j]
    __shared__ float Vs [64][64];  // [j][d]

    const int tid = threadIdx.x;
    const int tx = tid & 15, ty = tid >> 4;
    const int b = blockIdx.z, h = blockIdx.y;
    const int t0 = blockIdx.x << 6;
    const size_t bbase = (size_t)b * (CH * LEN);
    const int hoff = h << 6;

    // Load Q tile transposed with swizzle
    for (int idx = tid; idx < 1024; idx += 256) {
        int n = idx >> 4, ch = idx & 15, d = ch << 2;
        size_t off = bbase + (size_t)((t0 + n) >> 2) * LEN
                   + ((t0 + n) & 3) * 512 + hoff + d;
        float4 q4 = *(const float4*)(yq + off);
        int col = n ^ d;            // (d+j)&60 == d for j<4
        QsT[d + 0][col] = q4.x;
        QsT[d + 1][col] = q4.y;
        QsT[d + 2][col] = q4.z;
        QsT[d + 3][col] = q4.w;
    }

    float m[4], lsum[4], o[4][4];
    #pragma unroll
    for (int a = 0; a < 4; a++) {
        m[a] = -INFINITY; lsum[a] = 0.f;
        #pragma unroll
        for (int c = 0; c < 4; c++) o[a][c] = 0.f;
    }

    for (int j0 = 0; j0 < LEN; j0 += 64) {
        __syncthreads();
        for (int idx = tid; idx < 1024; idx += 256) {
            int r = idx >> 4, ch = idx & 15;
            int n = j0 + r;
            size_t off = bbase + (size_t)(n >> 2) * LEN + (n & 3) * 512 + hoff + (ch << 2);
            float4 k4 = *(const float4*)(yk + off);
            int sw = r ^ (ch << 2);
            KP[(ch << 2) + 0][sw] = k4.x;
            KP[(ch << 2) + 1][sw] = k4.y;
            KP[(ch << 2) + 2][sw] = k4.z;
            KP[(ch << 2) + 3][sw] = k4.w;
            *(float4*)&Vs[r][ch << 2] = *(const float4*)(yv + off);
        }
        __syncthreads();

        // S = Q @ K^T : 2x LDS.128 + 16 FMA per d
        float s[4][4] = {};
        #pragma unroll 16
        for (int d = 0; d < 64; d++) {
            const int dm = d & 60;
            float4 q4 = *(const float4*)&QsT[d][(ty << 2) ^ dm];
            float4 k4 = *(const float4*)&KP [d][(tx << 2) ^ dm];
            float qv[4] = {q4.x, q4.y, q4.z, q4.w};
            float kv[4] = {k4.x, k4.y, k4.z, k4.w};
            #pragma unroll
            for (int a = 0; a < 4; a++)
                #pragma unroll
                for (int c = 0; c < 4; c++)
                    s[a][c] = fmaf(qv[a], kv[c], s[a][c]);
        }
        __syncthreads();   // done reading KP; becomes P

        #pragma unroll
        for (int a = 0; a < 4; a++) {
            const float scale = 1.f / 64.f;
            float s0 = s[a][0] * scale, s1 = s[a][1] * scale;
            float s2 = s[a][2] * scale, s3 = s[a][3] * scale;
            float mx = fmaxf(fmaxf(s0, s1), fmaxf(s2, s3));
            mx = fmaxf(mx, __shfl_xor_sync(0xffffffffu, mx, 8));
            mx = fmaxf(mx, __shfl_xor_sync(0xffffffffu, mx, 4));
            mx = fmaxf(mx, __shfl_xor_sync(0xffffffffu, mx, 2));
            mx = fmaxf(mx, __shfl_xor_sync(0xffffffffu, mx, 1));
            float newm = fmaxf(m[a], mx);
            float corr = __expf(m[a] - newm);
            float p0 = __expf(s0 - newm);
            float p1 = __expf(s1 - newm);
            float p2 = __expf(s2 - newm);
            float p3 = __expf(s3 - newm);
            float rs = (p0 + p1) + (p2 + p3);
            rs += __shfl_xor_sync(0xffffffffu, rs, 8);
            rs += __shfl_xor_sync(0xffffffffu, rs, 4);
            rs += __shfl_xor_sync(0xffffffffu, rs, 2);
            rs += __shfl_xor_sync(0xffffffffu, rs, 1);
            lsum[a] = lsum[a] * corr + rs;
            m[a] = newm;
            o[a][0] *= corr; o[a][1] *= corr; o[a][2] *= corr; o[a][3] *= corr;
            float4 p4 = make_float4(p0, p1, p2, p3);
            *(float4*)&KP[(ty << 2) + a][tx << 2] = p4;
        }
        __syncthreads();

        // O += P @ V : 4 broadcast LDS + 1 LDS.128 + 16 FMA per j
        #pragma unroll 8
        for (int j = 0; j < 64; j++) {
            float pv[4];
            #pragma unroll
            for (int a = 0; a < 4; a++) pv[a] = KP[(ty << 2) + a][j];
            float4 v4 = *(const float4*)&Vs[j][tx << 2];
            float vv[4] = {v4.x, v4.y, v4.z, v4.w};
            #pragma unroll
            for (int a = 0; a < 4; a++)
                #pragma unroll
                for (int c = 0; c < 4; c++)
                    o[a][c] = fmaf(pv[a], vv[c], o[a][c]);
        }
    }

    #pragma unroll
    for (int a = 0; a < 4; a++) {
        float inv = 1.f / lsum[a];
        int n = t0 + (ty << 2) + a;
        size_t off = bbase + (size_t)(n >> 2) * LEN + (n & 3) * 512 + hoff + (tx << 2);
        float4 r4 = make_float4(o[a][0] * inv, o[a][1] * inv,
                                o[a][2] * inv, o[a][3] * inv);
        *(float4*)(z + off) = r4;
    }
}

// ---------------------------------------------------------------------------
extern "C" void kernel_launch(void* const* d_in, const int* in_sizes, int n_in,
                              void* d_out, int out_size)
{
    const float* q    = (const float*)d_in[0];
    const float* k    = (const float*)d_in[1];
    const float* v    = (const float*)d_in[2];
    const float* wq_w = (const float*)d_in[3];
    const float* wq_b = (const float*)d_in[4];
    const float* wk_w = (const float*)d_in[5];
    const float* wk_b = (const float*)d_in[6];
    const float* wv_w = (const float*)d_in[7];
    const float* wv_b = (const float*)d_in[8];
    const float* fc_w = (const float*)d_in[9];
    const float* fc_b = (const float*)d_in[10];
    float* out = (float*)d_out;

    float *yq, *yk, *yv, *zb;
    cudaGetSymbolAddress((void**)&yq, g_yq);
    cudaGetSymbolAddress((void**)&yk, g_yk);
    cudaGetSymbolAddress((void**)&yv, g_yv);
    cudaGetSymbolAddress((void**)&zb, g_z);

    dim3 blk(256);
    dim3 gqkv(LEN / 64, CH / 64, 3 * BATCH);   // (32, 8, 12)
    conv_qkv_k<<<gqkv, blk>>>(q, k, v, wq_w, wk_w, wv_w, wq_b, wk_b, wv_b,
                              yq, yk, yv);

    dim3 agrid(LEN / 64, 8, BATCH);
    attn_k<<<agrid, blk>>>(yq, yk, yv, zb);

    dim3 gfc(LEN / 64, CH / 64, BATCH);
    conv1d_k<<<gfc, blk>>>(zb, fc_w, fc_b, out);
}